// round 15
// baseline (speedup 1.0000x reference)
#include <cuda_runtime.h>
#include <cuda_fp16.h>
#include <cstdint>

#define F_IN 512
#define HID  128
#define OUTF 40
#define MAXN 50000
#define MAXE 800000
#define NTILE 256

// ---- device scratch (static; no allocation; zero-initialized at load) ----
__device__ uint32_t g_xwh[MAXN * 64];   // X @ W1 as packed half2 (12.8 MB)
__device__ float g_h[MAXN * HID];
__device__ uint32_t g_t2h[MAXN * 20];   // h @ W2 as packed half2 (4 MB)
__device__ int   g_counts[MAXN];
__device__ int   g_rowstart[MAXN + 1];  // +1: sentinel = E
__device__ int   g_cur[MAXN];
__device__ int2  g_edge[MAXE];
__device__ unsigned g_tstate[256];
__device__ int   g_ticket;
// W1 pre-converted (tf32, RNA-rounded) laid out as the per-kc smem B image
__device__ __align__(16) uint32_t g_wtf[32 * 2176];

__device__ __forceinline__ uint32_t f2tf(float f) {
    uint32_t u;
    asm("cvt.rna.tf32.f32 %0, %1;" : "=r"(u) : "f"(f));
    return u;
}
// pack two fp32 -> f16x2 (first arg = lower half)
__device__ __forceinline__ uint32_t packh2(float lo, float hi) {
    uint32_t d;
    asm("cvt.rn.f16x2.f32 %0, %1, %2;" : "=r"(d) : "f"(hi), "f"(lo));
    return d;
}

// ============ CSR: hist (side stream) =======================================
__global__ void hist_kernel(const int* __restrict__ dst, int E) {
    int e4 = (blockIdx.x * blockDim.x + threadIdx.x) * 4;
    if (e4 + 3 < E) {
        int4 d = *(const int4*)(dst + e4);
        atomicAdd(&g_counts[d.x], 1);
        atomicAdd(&g_counts[d.y], 1);
        atomicAdd(&g_counts[d.z], 1);
        atomicAdd(&g_counts[d.w], 1);
    } else {
        for (int e = e4; e < E; ++e) atomicAdd(&g_counts[dst[e]], 1);
    }
}

// ============ W1 prep (main stream, feeds gemm1) ============================
__global__ void w1_prep_kernel(const float* __restrict__ W) {
    int idx = blockIdx.x * 256 + threadIdx.x;
    int k = idx >> 7, col = idx & 127;
    g_wtf[(k >> 4) * 2176 + (k & 15) * 136 + col] = f2tf(W[idx]);
}

// ============ CSR: single-pass scan (decoupled lookback) + sentinel =========
__global__ void scan_kernel(int M) {
    __shared__ int s[NTILE];
    __shared__ int s_bid;
    __shared__ int s_prefix;
    int tid = threadIdx.x;
    if (tid == 0) s_bid = atomicAdd(&g_ticket, 1);
    __syncthreads();
    int bid = s_bid;
    int i = bid * NTILE + tid;
    int v = (i < M) ? g_counts[i] : 0;
    s[tid] = v;
    __syncthreads();
    #pragma unroll
    for (int off = 1; off < NTILE; off <<= 1) {
        int t = (tid >= off) ? s[tid - off] : 0;
        __syncthreads();
        s[tid] += t;
        __syncthreads();
    }
    if (tid == 0) {
        int agg = s[NTILE - 1];
        if (bid == 0) {
            atomicExch(&g_tstate[0], ((unsigned)agg << 2) | 2u);
            s_prefix = 0;
        } else {
            atomicExch(&g_tstate[bid], ((unsigned)agg << 2) | 1u);
            int run = 0;
            int j = bid - 1;
            while (true) {
                unsigned st;
                do { st = atomicOr(&g_tstate[j], 0u); } while ((st & 3u) == 0u);
                run += (int)(st >> 2);
                if ((st & 3u) == 2u) break;
                --j;
            }
            s_prefix = run;
            atomicExch(&g_tstate[bid], ((unsigned)(run + agg) << 2) | 2u);
        }
    }
    __syncthreads();
    if (i < M) {
        int excl = s_prefix + s[tid] - v;
        g_rowstart[i] = excl;
        g_cur[i] = excl;
        if (i == M - 1) g_rowstart[M] = excl + v;   // sentinel = E
    }
}

// ============ CSR: fill (ATOMG slot assignment) =============================
__global__ void fill_kernel(const int* __restrict__ dst, const int* __restrict__ src,
                            const float* __restrict__ ew, int E) {
    int e4 = (blockIdx.x * blockDim.x + threadIdx.x) * 4;
    if (e4 + 3 < E) {
        int4   d = *(const int4*)(dst + e4);
        int4   s = *(const int4*)(src + e4);
        float4 w = *(const float4*)(ew + e4);
        int p0 = atomicAdd(&g_cur[d.x], 1);
        int p1 = atomicAdd(&g_cur[d.y], 1);
        int p2 = atomicAdd(&g_cur[d.z], 1);
        int p3 = atomicAdd(&g_cur[d.w], 1);
        g_edge[p0] = make_int2(s.x, __float_as_int(w.x));
        g_edge[p1] = make_int2(s.y, __float_as_int(w.y));
        g_edge[p2] = make_int2(s.z, __float_as_int(w.z));
        g_edge[p3] = make_int2(s.w, __float_as_int(w.w));
    } else {
        for (int e = e4; e < E; ++e) {
            int p = atomicAdd(&g_cur[dst[e]], 1);
            g_edge[p] = make_int2(src[e], __float_as_int(ew[e]));
        }
    }
}

// ============ cleanup (side stream, after fill; hidden under gemm1) =========
__global__ void cleanup_kernel(int M) {
    int i = blockIdx.x * blockDim.x + threadIdx.x;
    if (i < M) g_counts[i] = 0;
    if (i < 256) g_tstate[i] = 0;
    if (i == 0) g_ticket = 0;
}

// ================= GEMM1 (mma.sync tf32, cp.async 4-stage pipeline) =========
#define AS_STRIDE 20
#define BS_STRIDE 136
#define STAGE_WORDS (128 * AS_STRIDE + 16 * BS_STRIDE)   // 4736
#define STAGE_BYTES (STAGE_WORDS * 4)                    // 18944
#define NSTAGE 4
#define GEMM1_SMEM (STAGE_BYTES * NSTAGE)                // 75776

__device__ __forceinline__ void cp16(uint32_t saddr, const void* gptr, int srcbytes) {
    asm volatile("cp.async.ca.shared.global [%0], [%1], 16, %2;"
                 :: "r"(saddr), "l"(gptr), "r"(srcbytes));
}
#define CP_COMMIT() asm volatile("cp.async.commit_group;" ::: "memory")
#define CP_WAIT(n)  asm volatile("cp.async.wait_group %0;" :: "n"(n) : "memory")

__device__ __forceinline__ uint32_t smem_u32(const void* p) {
    uint32_t a;
    asm("{ .reg .u64 t; cvta.to.shared.u64 t, %1; cvt.u32.u64 %0, t; }" : "=r"(a) : "l"(p));
    return a;
}

__global__ __launch_bounds__(256, 2) void gemm1_tc_kernel(
    const float* __restrict__ X, int M)
{
    extern __shared__ uint32_t smem[];
    const uint32_t sb = smem_u32(smem);

    const int tid  = threadIdx.x;
    const int lane = tid & 31;
    const int wid  = tid >> 5;
    const int wm   = wid >> 1;
    const int wn   = wid & 1;
    const int g    = lane >> 2;
    const int la   = lane & 3;
    const int rowBase = blockIdx.x * 128;

    const int aRow = tid >> 2;
    const int aC4  = tid & 3;

    float acc[2][8][4];
    #pragma unroll
    for (int mt = 0; mt < 2; ++mt)
        #pragma unroll
        for (int nt = 0; nt < 8; ++nt)
            #pragma unroll
            for (int r = 0; r < 4; ++r) acc[mt][nt][r] = 0.f;

    #define LOAD_STAGE(st, kc) {                                                  \
        uint32_t abase = sb + (st) * STAGE_BYTES;                                  \
        _Pragma("unroll")                                                          \
        for (int i = 0; i < 2; ++i) {                                             \
            int row = aRow + i * 64;                                              \
            int r = rowBase + row;                                                \
            const float* src = X + (size_t)r * F_IN + (kc) * 16 + aC4 * 4;        \
            cp16(abase + (row * AS_STRIDE + aC4 * 4) * 4, src, (r < M) ? 16 : 0); \
        }                                                                          \
        uint32_t bbase = abase + 128 * AS_STRIDE * 4;                              \
        const uint32_t* bsrc = g_wtf + (kc) * 2176;                                \
        _Pragma("unroll")                                                          \
        for (int i = 0; i < 3; ++i) {                                             \
            int idx = i * 256 + tid;                                              \
            if (idx < 544) cp16(bbase + idx * 16, bsrc + idx * 4, 16);            \
        }                                                                          \
        CP_COMMIT();                                                               \
    }

    LOAD_STAGE(0, 0);
    LOAD_STAGE(1, 1);
    LOAD_STAGE(2, 2);

    const int NCHUNK = F_IN / 16;   // 32
    for (int kc = 0; kc < NCHUNK; ++kc) {
        CP_WAIT(2);
        __syncthreads();

        if (kc + 3 < NCHUNK) LOAD_STAGE((kc + 3) & 3, kc + 3);

        const uint32_t* As = smem + (kc & 3) * STAGE_WORDS;
        const uint32_t* Bs = As + 128 * AS_STRIDE;

        #pragma unroll
        for (int ks = 0; ks < 2; ++ks) {
            uint32_t af[2][4], bf[8][2];
            #pragma unroll
            for (int mt = 0; mt < 2; ++mt) {
                int rb = wm * 32 + mt * 16;
                af[mt][0] = As[(rb + g)     * AS_STRIDE + ks * 8 + la];
                af[mt][1] = As[(rb + 8 + g) * AS_STRIDE + ks * 8 + la];
                af[mt][2] = As[(rb + g)     * AS_STRIDE + ks * 8 + la + 4];
                af[mt][3] = As[(rb + 8 + g) * AS_STRIDE + ks * 8 + la + 4];
            }
            #pragma unroll
            for (int nt = 0; nt < 8; ++nt) {
                int col = wn * 64 + nt * 8 + g;
                bf[nt][0] = Bs[(ks * 8 + la)     * BS_STRIDE + col];
                bf[nt][1] = Bs[(ks * 8 + la + 4) * BS_STRIDE + col];
            }
            #pragma unroll
            for (int mt = 0; mt < 2; ++mt)
                #pragma unroll
                for (int nt = 0; nt < 8; ++nt) {
                    float* c = acc[mt][nt];
                    asm volatile(
                        "mma.sync.aligned.m16n8k8.row.col.f32.tf32.tf32.f32 "
                        "{%0,%1,%2,%3}, {%4,%5,%6,%7}, {%8,%9}, {%0,%1,%2,%3};\n"
                        : "+f"(c[0]), "+f"(c[1]), "+f"(c[2]), "+f"(c[3])
                        : "r"(af[mt][0]), "r"(af[mt][1]), "r"(af[mt][2]), "r"(af[mt][3]),
                          "r"(bf[nt][0]), "r"(bf[nt][1]));
                }
        }
    }

    // epilogue: pack C pairs to half2 and store
    #pragma unroll
    for (int mt = 0; mt < 2; ++mt) {
        int r0 = rowBase + wm * 32 + mt * 16 + g;
        #pragma unroll
        for (int nt = 0; nt < 8; ++nt) {
            int colh = wn * 32 + nt * 4 + la;
            if (r0 < M)
                g_xwh[(size_t)r0 * 64 + colh] = packh2(acc[mt][nt][0], acc[mt][nt][1]);
            if (r0 + 8 < M)
                g_xwh[(size_t)(r0 + 8) * 64 + colh] = packh2(acc[mt][nt][2], acc[mt][nt][3]);
        }
    }
    #undef LOAD_STAGE
}

// == SpMM1: HALF-WARP (16 lanes) per row, uint4 gathers, fused relu/bias/mask =
__global__ __launch_bounds__(256) void spmm1_kernel(
    const float* __restrict__ b1, const float* __restrict__ mask, int M)
{
    int hw = (blockIdx.x * blockDim.x + threadIdx.x) >> 4;   // row id
    int l  = threadIdx.x & 15;
    int hb = threadIdx.x & 16;        // half base within warp (0 or 16)
    bool valid = (hw < M);
    int row = valid ? hw : 0;
    int start = g_rowstart[row];
    int deg = valid ? (g_rowstart[row + 1] - start) : 0;
    float4 acc0 = make_float4(0.f, 0.f, 0.f, 0.f);
    float4 acc1 = make_float4(0.f, 0.f, 0.f, 0.f);
    const int wbase = l << 2;         // uint4 word base (8 cols)

    for (int base = 0; base < deg; base += 16) {
        int rem = deg - base;
        int cnt = rem < 16 ? rem : 16;
        int s = 0; float w = 0.f;
        if (l < cnt) {
            int2 ev = g_edge[start + base + l];
            s = ev.x;
            w = __int_as_float(ev.y);
        }
        int i = 0;
        for (; i + 4 <= cnt; i += 4) {
            int   s0 = __shfl_sync(0xffffffffu, s, hb + i);
            int   s1 = __shfl_sync(0xffffffffu, s, hb + i + 1);
            int   s2 = __shfl_sync(0xffffffffu, s, hb + i + 2);
            int   s3 = __shfl_sync(0xffffffffu, s, hb + i + 3);
            float w0 = __shfl_sync(0xffffffffu, w, hb + i);
            float w1 = __shfl_sync(0xffffffffu, w, hb + i + 1);
            float w2 = __shfl_sync(0xffffffffu, w, hb + i + 2);
            float w3 = __shfl_sync(0xffffffffu, w, hb + i + 3);
            uint4 u0 = *(const uint4*)(g_xwh + (size_t)s0 * 64 + wbase);
            uint4 u1 = *(const uint4*)(g_xwh + (size_t)s1 * 64 + wbase);
            uint4 u2 = *(const uint4*)(g_xwh + (size_t)s2 * 64 + wbase);
            uint4 u3 = *(const uint4*)(g_xwh + (size_t)s3 * 64 + wbase);
            #define ACC(u, ww) {                                             \
                float2 f0 = __half22float2(*(const __half2*)&(u).x);         \
                float2 f1 = __half22float2(*(const __half2*)&(u).y);         \
                float2 f2 = __half22float2(*(const __half2*)&(u).z);         \
                float2 f3 = __half22float2(*(const __half2*)&(u).w);         \
                acc0.x = fmaf(ww, f0.x, acc0.x); acc0.y = fmaf(ww, f0.y, acc0.y); \
                acc0.z = fmaf(ww, f1.x, acc0.z); acc0.w = fmaf(ww, f1.y, acc0.w); \
                acc1.x = fmaf(ww, f2.x, acc1.x); acc1.y = fmaf(ww, f2.y, acc1.y); \
                acc1.z = fmaf(ww, f3.x, acc1.z); acc1.w = fmaf(ww, f3.y, acc1.w); \
            }
            ACC(u0, w0); ACC(u1, w1); ACC(u2, w2); ACC(u3, w3);
        }
        for (; i < cnt; ++i) {
            int   ss = __shfl_sync(0xffffffffu, s, hb + i);
            float ww = __shfl_sync(0xffffffffu, w, hb + i);
            uint4 u = *(const uint4*)(g_xwh + (size_t)ss * 64 + wbase);
            ACC(u, ww);
        }
    }
    #undef ACC

    if (valid) {
        const int col = l << 3;
        float4 ba = *(const float4*)(b1 + col);
        float4 bb = *(const float4*)(b1 + col + 4);
        float4 ma = *(const float4*)(mask + (size_t)row * HID + col);
        float4 mb = *(const float4*)(mask + (size_t)row * HID + col + 4);
        float4 oa, ob;
        oa.x = fmaxf(acc0.x + ba.x, 0.f) * ma.x;
        oa.y = fmaxf(acc0.y + ba.y, 0.f) * ma.y;
        oa.z = fmaxf(acc0.z + ba.z, 0.f) * ma.z;
        oa.w = fmaxf(acc0.w + ba.w, 0.f) * ma.w;
        ob.x = fmaxf(acc1.x + bb.x, 0.f) * mb.x;
        ob.y = fmaxf(acc1.y + bb.y, 0.f) * mb.y;
        ob.z = fmaxf(acc1.z + bb.z, 0.f) * mb.z;
        ob.w = fmaxf(acc1.w + bb.w, 0.f) * mb.w;
        *(float4*)(g_h + (size_t)row * HID + col) = oa;
        *(float4*)(g_h + (size_t)row * HID + col + 4) = ob;
    }
}

// ============ GEMM2: [M,128] @ [128,40] -> packed fp16 t2 ===================
__global__ __launch_bounds__(256) void gemm2_kernel(const float* __restrict__ W2, int M)
{
    __shared__ float Ws[HID][OUTF];
    int tid = threadIdx.x;
    for (int i = tid; i < HID * OUTF; i += 256)
        Ws[i / OUTF][i % OUTF] = W2[i];
    __syncthreads();

    int r = blockIdx.x * 64 + (tid >> 2);
    int c0 = (tid & 3) * 10;
    if (r >= M) return;

    float acc[10] = {};
    const float4* hrow = (const float4*)(g_h + (size_t)r * HID);
    #pragma unroll 4
    for (int k4 = 0; k4 < HID / 4; ++k4) {
        float4 a = hrow[k4];
        int k = k4 * 4;
        #pragma unroll
        for (int j = 0; j < 10; ++j) acc[j] = fmaf(a.x, Ws[k + 0][c0 + j], acc[j]);
        #pragma unroll
        for (int j = 0; j < 10; ++j) acc[j] = fmaf(a.y, Ws[k + 1][c0 + j], acc[j]);
        #pragma unroll
        for (int j = 0; j < 10; ++j) acc[j] = fmaf(a.z, Ws[k + 2][c0 + j], acc[j]);
        #pragma unroll
        for (int j = 0; j < 10; ++j) acc[j] = fmaf(a.w, Ws[k + 3][c0 + j], acc[j]);
    }
    uint32_t* trow = g_t2h + (size_t)r * 20 + (c0 >> 1);
    #pragma unroll
    for (int j = 0; j < 5; ++j)
        trow[j] = packh2(acc[2 * j], acc[2 * j + 1]);
}

// ==== SpMM2 (OUT=40): warp per row, fp16 gathers, fused b2 ==================
__global__ __launch_bounds__(256) void spmm2_kernel(
    const float* __restrict__ b2, float* __restrict__ out, int M)
{
    int gw = (blockIdx.x * blockDim.x + threadIdx.x) >> 5;
    int lane = threadIdx.x & 31;
    if (gw >= M) return;
    int start = g_rowstart[gw];
    int deg = g_rowstart[gw + 1] - start;
    float2 acc = make_float2(0.f, 0.f);
    const bool act = (lane < 20);

    for (int base = 0; base < deg; base += 32) {
        int rem = deg - base;
        int cnt = rem < 32 ? rem : 32;
        int s = 0; float w = 0.f;
        if (lane < cnt) {
            int2 ev = g_edge[start + base + lane];
            s = ev.x;
            w = __int_as_float(ev.y);
        }
        int i = 0;
        for (; i + 4 <= cnt; i += 4) {
            int   s0 = __shfl_sync(0xffffffffu, s, i);
            int   s1 = __shfl_sync(0xffffffffu, s, i + 1);
            int   s2 = __shfl_sync(0xffffffffu, s, i + 2);
            int   s3 = __shfl_sync(0xffffffffu, s, i + 3);
            float w0 = __shfl_sync(0xffffffffu, w, i);
            float w1 = __shfl_sync(0xffffffffu, w, i + 1);
            float w2 = __shfl_sync(0xffffffffu, w, i + 2);
            float w3 = __shfl_sync(0xffffffffu, w, i + 3);
            if (act) {
                uint32_t u0 = g_t2h[(size_t)s0 * 20 + lane];
                uint32_t u1 = g_t2h[(size_t)s1 * 20 + lane];
                uint32_t u2 = g_t2h[(size_t)s2 * 20 + lane];
                uint32_t u3 = g_t2h[(size_t)s3 * 20 + lane];
                float2 v0 = __half22float2(*(const __half2*)&u0);
                float2 v1 = __half22float2(*(const __half2*)&u1);
                float2 v2 = __half22float2(*(const __half2*)&u2);
                float2 v3 = __half22float2(*(const __half2*)&u3);
                acc.x = fmaf(w0, v0.x, acc.x); acc.y = fmaf(w0, v0.y, acc.y);
                acc.x = fmaf(w1, v1.x, acc.x); acc.y = fmaf(w1, v1.y, acc.y);
                acc.x = fmaf(w2, v2.x, acc.x); acc.y = fmaf(w2, v2.y, acc.y);
                acc.x = fmaf(w3, v3.x, acc.x); acc.y = fmaf(w3, v3.y, acc.y);
            }
        }
        for (; i < cnt; ++i) {
            int   ss = __shfl_sync(0xffffffffu, s, i);
            float ww = __shfl_sync(0xffffffffu, w, i);
            if (act) {
                uint32_t u = g_t2h[(size_t)ss * 20 + lane];
                float2 v = __half22float2(*(const __half2*)&u);
                acc.x = fmaf(ww, v.x, acc.x);
                acc.y = fmaf(ww, v.y, acc.y);
            }
        }
    }

    if (act) {
        const int col = lane << 1;
        float2 b = *(const float2*)(b2 + col);
        float2 o = make_float2(acc.x + b.x, acc.y + b.y);
        *(float2*)(out + (size_t)gw * OUTF + col) = o;
    }
}

// ================= launch =================
extern "C" void kernel_launch(void* const* d_in, const int* in_sizes, int n_in,
                              void* d_out, int out_size)
{
    const float* x    = (const float*)d_in[0];
    const float* W1   = (const float*)d_in[1];
    const float* b1   = (const float*)d_in[2];
    const float* W2   = (const float*)d_in[3];
    const float* b2   = (const float*)d_in[4];
    const float* ew   = (const float*)d_in[5];
    const float* mask = (const float*)d_in[6];
    const int*   esrc = (const int*)d_in[7];
    const int*   edst = (const int*)d_in[8];
    float* out = (float*)d_out;

    const int M = in_sizes[0] / F_IN;   // 50000
    const int E = in_sizes[7];          // 800000

    const int nbM  = (M + NTILE - 1) / NTILE;
    const int nbE4 = (E / 4 + 255) / 256;

    // one-time setup (first call = correctness run, NOT captured)
    static cudaStream_t s_side = nullptr;
    static cudaEvent_t  s_fork = nullptr, s_join = nullptr;
    if (s_side == nullptr) {
        cudaFuncSetAttribute(gemm1_tc_kernel,
                             cudaFuncAttributeMaxDynamicSharedMemorySize, GEMM1_SMEM);
        cudaStreamCreateWithFlags(&s_side, cudaStreamNonBlocking);
        cudaEventCreateWithFlags(&s_fork, cudaEventDisableTiming);
        cudaEventCreateWithFlags(&s_join, cudaEventDisableTiming);
    }

    // fork: CSR chain (+cleanup) on side stream, concurrent with gemm1 on main
    cudaEventRecord(s_fork, 0);
    cudaStreamWaitEvent(s_side, s_fork, 0);
    hist_kernel<<<nbE4, 256, 0, s_side>>>(edst, E);
    scan_kernel<<<nbM, NTILE, 0, s_side>>>(M);
    fill_kernel<<<nbE4, 256, 0, s_side>>>(edst, esrc, ew, E);
    cleanup_kernel<<<nbM, 256, 0, s_side>>>(M);   // hidden under gemm1
    cudaEventRecord(s_join, s_side);

    // main: layer-1 dense path (independent of CSR)
    w1_prep_kernel<<<(F_IN * HID) / 256, 256>>>(W1);
    gemm1_tc_kernel<<<(M + 127) / 128, 256, GEMM1_SMEM>>>(x, M);

    // join: spmm1 needs both gemm1 (main) and CSR (side)
    cudaStreamWaitEvent(0, s_join, 0);
    spmm1_kernel<<<(M + 15) / 16, 256>>>(b1, mask, M);

    // layer 2
    gemm2_kernel<<<(M + 63) / 64, 256>>>(W2, M);
    spmm2_kernel<<<(M + 7) / 8, 256>>>(b2, out, M);
}

// round 17
// speedup vs baseline: 1.0749x; 1.0749x over previous
#include <cuda_runtime.h>
#include <cuda_fp16.h>
#include <cstdint>

#define F_IN 512
#define HID  128
#define OUTF 40
#define MAXN 50000
#define MAXE 800000
#define NTILE 256

// ---- device scratch (static; no allocation; zero-initialized at load) ----
__device__ uint32_t g_xwh[MAXN * 64];   // X @ W1 as packed half2 (12.8 MB)
__device__ float g_h[MAXN * HID];
__device__ uint32_t g_t2h[MAXN * 20];   // h @ W2 as packed half2 (4 MB)
__device__ int   g_counts[MAXN];
__device__ int   g_rowstart[MAXN + 1];  // +1: sentinel = E
__device__ int   g_cur[MAXN];
__device__ int2  g_edge[MAXE];
__device__ unsigned g_tstate[256];
__device__ int   g_ticket;
// W1 pre-converted (tf32, RNA-rounded) laid out as the per-kc smem B image
__device__ __align__(16) uint32_t g_wtf[32 * 2176];

__device__ __forceinline__ uint32_t f2tf(float f) {
    uint32_t u;
    asm("cvt.rna.tf32.f32 %0, %1;" : "=r"(u) : "f"(f));
    return u;
}
// pack two fp32 -> f16x2 (first arg = lower half)
__device__ __forceinline__ uint32_t packh2(float lo, float hi) {
    uint32_t d;
    asm("cvt.rn.f16x2.f32 %0, %1, %2;" : "=r"(d) : "f"(hi), "f"(lo));
    return d;
}

// ============ CSR: hist (side stream) =======================================
__global__ void hist_kernel(const int* __restrict__ dst, int E) {
    int e4 = (blockIdx.x * blockDim.x + threadIdx.x) * 4;
    if (e4 + 3 < E) {
        int4 d = *(const int4*)(dst + e4);
        atomicAdd(&g_counts[d.x], 1);
        atomicAdd(&g_counts[d.y], 1);
        atomicAdd(&g_counts[d.z], 1);
        atomicAdd(&g_counts[d.w], 1);
    } else {
        for (int e = e4; e < E; ++e) atomicAdd(&g_counts[dst[e]], 1);
    }
}

// ============ W1 prep (main stream, feeds gemm1) ============================
__global__ void w1_prep_kernel(const float* __restrict__ W) {
    int idx = blockIdx.x * 256 + threadIdx.x;
    int k = idx >> 7, col = idx & 127;
    g_wtf[(k >> 4) * 2176 + (k & 15) * 136 + col] = f2tf(W[idx]);
}

// ============ CSR: single-pass scan (decoupled lookback) + sentinel =========
__global__ void scan_kernel(int M) {
    __shared__ int s[NTILE];
    __shared__ int s_bid;
    __shared__ int s_prefix;
    int tid = threadIdx.x;
    if (tid == 0) s_bid = atomicAdd(&g_ticket, 1);
    __syncthreads();
    int bid = s_bid;
    int i = bid * NTILE + tid;
    int v = (i < M) ? g_counts[i] : 0;
    s[tid] = v;
    __syncthreads();
    #pragma unroll
    for (int off = 1; off < NTILE; off <<= 1) {
        int t = (tid >= off) ? s[tid - off] : 0;
        __syncthreads();
        s[tid] += t;
        __syncthreads();
    }
    if (tid == 0) {
        int agg = s[NTILE - 1];
        if (bid == 0) {
            atomicExch(&g_tstate[0], ((unsigned)agg << 2) | 2u);
            s_prefix = 0;
        } else {
            atomicExch(&g_tstate[bid], ((unsigned)agg << 2) | 1u);
            int run = 0;
            int j = bid - 1;
            while (true) {
                unsigned st;
                do { st = atomicOr(&g_tstate[j], 0u); } while ((st & 3u) == 0u);
                run += (int)(st >> 2);
                if ((st & 3u) == 2u) break;
                --j;
            }
            s_prefix = run;
            atomicExch(&g_tstate[bid], ((unsigned)(run + agg) << 2) | 2u);
        }
    }
    __syncthreads();
    if (i < M) {
        int excl = s_prefix + s[tid] - v;
        g_rowstart[i] = excl;
        g_cur[i] = excl;
        if (i == M - 1) g_rowstart[M] = excl + v;   // sentinel = E
    }
}

// ============ CSR: fill (ATOMG slot assignment) =============================
__global__ void fill_kernel(const int* __restrict__ dst, const int* __restrict__ src,
                            const float* __restrict__ ew, int E) {
    int e4 = (blockIdx.x * blockDim.x + threadIdx.x) * 4;
    if (e4 + 3 < E) {
        int4   d = *(const int4*)(dst + e4);
        int4   s = *(const int4*)(src + e4);
        float4 w = *(const float4*)(ew + e4);
        int p0 = atomicAdd(&g_cur[d.x], 1);
        int p1 = atomicAdd(&g_cur[d.y], 1);
        int p2 = atomicAdd(&g_cur[d.z], 1);
        int p3 = atomicAdd(&g_cur[d.w], 1);
        g_edge[p0] = make_int2(s.x, __float_as_int(w.x));
        g_edge[p1] = make_int2(s.y, __float_as_int(w.y));
        g_edge[p2] = make_int2(s.z, __float_as_int(w.z));
        g_edge[p3] = make_int2(s.w, __float_as_int(w.w));
    } else {
        for (int e = e4; e < E; ++e) {
            int p = atomicAdd(&g_cur[dst[e]], 1);
            g_edge[p] = make_int2(src[e], __float_as_int(ew[e]));
        }
    }
}

// ============ cleanup (side stream, after fill; hidden under gemm1) =========
__global__ void cleanup_kernel(int M) {
    int i = blockIdx.x * blockDim.x + threadIdx.x;
    if (i < M) g_counts[i] = 0;
    if (i < 256) g_tstate[i] = 0;
    if (i == 0) g_ticket = 0;
}

// ================= GEMM1 (mma.sync tf32, cp.async 4-stage pipeline) =========
#define AS_STRIDE 20
#define BS_STRIDE 136
#define STAGE_WORDS (128 * AS_STRIDE + 16 * BS_STRIDE)   // 4736
#define STAGE_BYTES (STAGE_WORDS * 4)                    // 18944
#define NSTAGE 4
#define GEMM1_SMEM (STAGE_BYTES * NSTAGE)                // 75776

__device__ __forceinline__ void cp16(uint32_t saddr, const void* gptr, int srcbytes) {
    asm volatile("cp.async.ca.shared.global [%0], [%1], 16, %2;"
                 :: "r"(saddr), "l"(gptr), "r"(srcbytes));
}
#define CP_COMMIT() asm volatile("cp.async.commit_group;" ::: "memory")
#define CP_WAIT(n)  asm volatile("cp.async.wait_group %0;" :: "n"(n) : "memory")

__device__ __forceinline__ uint32_t smem_u32(const void* p) {
    uint32_t a;
    asm("{ .reg .u64 t; cvta.to.shared.u64 t, %1; cvt.u32.u64 %0, t; }" : "=r"(a) : "l"(p));
    return a;
}

__global__ __launch_bounds__(256, 2) void gemm1_tc_kernel(
    const float* __restrict__ X, int M)
{
    extern __shared__ uint32_t smem[];
    const uint32_t sb = smem_u32(smem);

    const int tid  = threadIdx.x;
    const int lane = tid & 31;
    const int wid  = tid >> 5;
    const int wm   = wid >> 1;
    const int wn   = wid & 1;
    const int g    = lane >> 2;
    const int la   = lane & 3;
    const int rowBase = blockIdx.x * 128;

    const int aRow = tid >> 2;
    const int aC4  = tid & 3;

    float acc[2][8][4];
    #pragma unroll
    for (int mt = 0; mt < 2; ++mt)
        #pragma unroll
        for (int nt = 0; nt < 8; ++nt)
            #pragma unroll
            for (int r = 0; r < 4; ++r) acc[mt][nt][r] = 0.f;

    #define LOAD_STAGE(st, kc) {                                                  \
        uint32_t abase = sb + (st) * STAGE_BYTES;                                  \
        _Pragma("unroll")                                                          \
        for (int i = 0; i < 2; ++i) {                                             \
            int row = aRow + i * 64;                                              \
            int r = rowBase + row;                                                \
            const float* src = X + (size_t)r * F_IN + (kc) * 16 + aC4 * 4;        \
            cp16(abase + (row * AS_STRIDE + aC4 * 4) * 4, src, (r < M) ? 16 : 0); \
        }                                                                          \
        uint32_t bbase = abase + 128 * AS_STRIDE * 4;                              \
        const uint32_t* bsrc = g_wtf + (kc) * 2176;                                \
        _Pragma("unroll")                                                          \
        for (int i = 0; i < 3; ++i) {                                             \
            int idx = i * 256 + tid;                                              \
            if (idx < 544) cp16(bbase + idx * 16, bsrc + idx * 4, 16);            \
        }                                                                          \
        CP_COMMIT();                                                               \
    }

    LOAD_STAGE(0, 0);
    LOAD_STAGE(1, 1);
    LOAD_STAGE(2, 2);

    const int NCHUNK = F_IN / 16;   // 32
    for (int kc = 0; kc < NCHUNK; ++kc) {
        CP_WAIT(2);
        __syncthreads();

        if (kc + 3 < NCHUNK) LOAD_STAGE((kc + 3) & 3, kc + 3);

        const uint32_t* As = smem + (kc & 3) * STAGE_WORDS;
        const uint32_t* Bs = As + 128 * AS_STRIDE;

        #pragma unroll
        for (int ks = 0; ks < 2; ++ks) {
            uint32_t af[2][4], bf[8][2];
            #pragma unroll
            for (int mt = 0; mt < 2; ++mt) {
                int rb = wm * 32 + mt * 16;
                af[mt][0] = As[(rb + g)     * AS_STRIDE + ks * 8 + la];
                af[mt][1] = As[(rb + 8 + g) * AS_STRIDE + ks * 8 + la];
                af[mt][2] = As[(rb + g)     * AS_STRIDE + ks * 8 + la + 4];
                af[mt][3] = As[(rb + 8 + g) * AS_STRIDE + ks * 8 + la + 4];
            }
            #pragma unroll
            for (int nt = 0; nt < 8; ++nt) {
                int col = wn * 64 + nt * 8 + g;
                bf[nt][0] = Bs[(ks * 8 + la)     * BS_STRIDE + col];
                bf[nt][1] = Bs[(ks * 8 + la + 4) * BS_STRIDE + col];
            }
            #pragma unroll
            for (int mt = 0; mt < 2; ++mt)
                #pragma unroll
                for (int nt = 0; nt < 8; ++nt) {
                    float* c = acc[mt][nt];
                    asm volatile(
                        "mma.sync.aligned.m16n8k8.row.col.f32.tf32.tf32.f32 "
                        "{%0,%1,%2,%3}, {%4,%5,%6,%7}, {%8,%9}, {%0,%1,%2,%3};\n"
                        : "+f"(c[0]), "+f"(c[1]), "+f"(c[2]), "+f"(c[3])
                        : "r"(af[mt][0]), "r"(af[mt][1]), "r"(af[mt][2]), "r"(af[mt][3]),
                          "r"(bf[nt][0]), "r"(bf[nt][1]));
                }
        }
    }

    // epilogue: pack C pairs to half2 and store
    #pragma unroll
    for (int mt = 0; mt < 2; ++mt) {
        int r0 = rowBase + wm * 32 + mt * 16 + g;
        #pragma unroll
        for (int nt = 0; nt < 8; ++nt) {
            int colh = wn * 32 + nt * 4 + la;
            if (r0 < M)
                g_xwh[(size_t)r0 * 64 + colh] = packh2(acc[mt][nt][0], acc[mt][nt][1]);
            if (r0 + 8 < M)
                g_xwh[(size_t)(r0 + 8) * 64 + colh] = packh2(acc[mt][nt][2], acc[mt][nt][3]);
        }
    }
    #undef LOAD_STAGE
}

// ==== SpMM1: full warp per row, uint2 fp16 gathers, fused relu/bias/mask ====
__global__ __launch_bounds__(256) void spmm1_kernel(
    const float* __restrict__ b1, const float* __restrict__ mask, int M)
{
    int gw = (blockIdx.x * blockDim.x + threadIdx.x) >> 5;
    int lane = threadIdx.x & 31;
    if (gw >= M) return;
    int start = g_rowstart[gw];
    int deg = g_rowstart[gw + 1] - start;
    float4 acc = make_float4(0.f, 0.f, 0.f, 0.f);
    const int colh = lane << 1;        // half2 word base (covers cols 4*lane..4*lane+3)

    for (int base = 0; base < deg; base += 32) {
        int rem = deg - base;
        int cnt = rem < 32 ? rem : 32;
        int s = 0; float w = 0.f;
        if (lane < cnt) {
            int2 ev = g_edge[start + base + lane];
            s = ev.x;
            w = __int_as_float(ev.y);
        }
        int i = 0;
        for (; i + 4 <= cnt; i += 4) {
            int   s0 = __shfl_sync(0xffffffffu, s, i);
            int   s1 = __shfl_sync(0xffffffffu, s, i + 1);
            int   s2 = __shfl_sync(0xffffffffu, s, i + 2);
            int   s3 = __shfl_sync(0xffffffffu, s, i + 3);
            float w0 = __shfl_sync(0xffffffffu, w, i);
            float w1 = __shfl_sync(0xffffffffu, w, i + 1);
            float w2 = __shfl_sync(0xffffffffu, w, i + 2);
            float w3 = __shfl_sync(0xffffffffu, w, i + 3);
            uint2 u0 = *(const uint2*)(g_xwh + (size_t)s0 * 64 + colh);
            uint2 u1 = *(const uint2*)(g_xwh + (size_t)s1 * 64 + colh);
            uint2 u2 = *(const uint2*)(g_xwh + (size_t)s2 * 64 + colh);
            uint2 u3 = *(const uint2*)(g_xwh + (size_t)s3 * 64 + colh);
            float2 a0 = __half22float2(*(const __half2*)&u0.x);
            float2 b0 = __half22float2(*(const __half2*)&u0.y);
            float2 a1 = __half22float2(*(const __half2*)&u1.x);
            float2 b1f = __half22float2(*(const __half2*)&u1.y);
            float2 a2 = __half22float2(*(const __half2*)&u2.x);
            float2 b2f = __half22float2(*(const __half2*)&u2.y);
            float2 a3 = __half22float2(*(const __half2*)&u3.x);
            float2 b3f = __half22float2(*(const __half2*)&u3.y);
            acc.x = fmaf(w0, a0.x, acc.x); acc.y = fmaf(w0, a0.y, acc.y);
            acc.z = fmaf(w0, b0.x, acc.z); acc.w = fmaf(w0, b0.y, acc.w);
            acc.x = fmaf(w1, a1.x, acc.x); acc.y = fmaf(w1, a1.y, acc.y);
            acc.z = fmaf(w1, b1f.x, acc.z); acc.w = fmaf(w1, b1f.y, acc.w);
            acc.x = fmaf(w2, a2.x, acc.x); acc.y = fmaf(w2, a2.y, acc.y);
            acc.z = fmaf(w2, b2f.x, acc.z); acc.w = fmaf(w2, b2f.y, acc.w);
            acc.x = fmaf(w3, a3.x, acc.x); acc.y = fmaf(w3, a3.y, acc.y);
            acc.z = fmaf(w3, b3f.x, acc.z); acc.w = fmaf(w3, b3f.y, acc.w);
        }
        for (; i < cnt; ++i) {
            int   ss = __shfl_sync(0xffffffffu, s, i);
            float ww = __shfl_sync(0xffffffffu, w, i);
            uint2 u = *(const uint2*)(g_xwh + (size_t)ss * 64 + colh);
            float2 a = __half22float2(*(const __half2*)&u.x);
            float2 b = __half22float2(*(const __half2*)&u.y);
            acc.x = fmaf(ww, a.x, acc.x);
            acc.y = fmaf(ww, a.y, acc.y);
            acc.z = fmaf(ww, b.x, acc.z);
            acc.w = fmaf(ww, b.y, acc.w);
        }
    }

    const int col = lane << 2;
    float4 b = *(const float4*)(b1 + col);
    float4 m = *(const float4*)(mask + (size_t)gw * HID + col);
    float4 o;
    o.x = fmaxf(acc.x + b.x, 0.f) * m.x;
    o.y = fmaxf(acc.y + b.y, 0.f) * m.y;
    o.z = fmaxf(acc.z + b.z, 0.f) * m.z;
    o.w = fmaxf(acc.w + b.w, 0.f) * m.w;
    *(float4*)(g_h + (size_t)gw * HID + col) = o;
}

// ============ GEMM2: [M,128] @ [128,40] -> packed fp16 t2 ===================
__global__ __launch_bounds__(256) void gemm2_kernel(const float* __restrict__ W2, int M)
{
    __shared__ float Ws[HID][OUTF];
    int tid = threadIdx.x;
    for (int i = tid; i < HID * OUTF; i += 256)
        Ws[i / OUTF][i % OUTF] = W2[i];
    __syncthreads();

    int r = blockIdx.x * 64 + (tid >> 2);
    int c0 = (tid & 3) * 10;
    if (r >= M) return;

    float acc[10] = {};
    const float4* hrow = (const float4*)(g_h + (size_t)r * HID);
    #pragma unroll 4
    for (int k4 = 0; k4 < HID / 4; ++k4) {
        float4 a = hrow[k4];
        int k = k4 * 4;
        #pragma unroll
        for (int j = 0; j < 10; ++j) acc[j] = fmaf(a.x, Ws[k + 0][c0 + j], acc[j]);
        #pragma unroll
        for (int j = 0; j < 10; ++j) acc[j] = fmaf(a.y, Ws[k + 1][c0 + j], acc[j]);
        #pragma unroll
        for (int j = 0; j < 10; ++j) acc[j] = fmaf(a.z, Ws[k + 2][c0 + j], acc[j]);
        #pragma unroll
        for (int j = 0; j < 10; ++j) acc[j] = fmaf(a.w, Ws[k + 3][c0 + j], acc[j]);
    }
    uint32_t* trow = g_t2h + (size_t)r * 20 + (c0 >> 1);
    #pragma unroll
    for (int j = 0; j < 5; ++j)
        trow[j] = packh2(acc[2 * j], acc[2 * j + 1]);
}

// ==== SpMM2 (OUT=40): warp per row, fp16 gathers, fused b2 ==================
__global__ __launch_bounds__(256) void spmm2_kernel(
    const float* __restrict__ b2, float* __restrict__ out, int M)
{
    int gw = (blockIdx.x * blockDim.x + threadIdx.x) >> 5;
    int lane = threadIdx.x & 31;
    if (gw >= M) return;
    int start = g_rowstart[gw];
    int deg = g_rowstart[gw + 1] - start;
    float2 acc = make_float2(0.f, 0.f);
    const bool act = (lane < 20);

    for (int base = 0; base < deg; base += 32) {
        int rem = deg - base;
        int cnt = rem < 32 ? rem : 32;
        int s = 0; float w = 0.f;
        if (lane < cnt) {
            int2 ev = g_edge[start + base + lane];
            s = ev.x;
            w = __int_as_float(ev.y);
        }
        int i = 0;
        for (; i + 4 <= cnt; i += 4) {
            int   s0 = __shfl_sync(0xffffffffu, s, i);
            int   s1 = __shfl_sync(0xffffffffu, s, i + 1);
            int   s2 = __shfl_sync(0xffffffffu, s, i + 2);
            int   s3 = __shfl_sync(0xffffffffu, s, i + 3);
            float w0 = __shfl_sync(0xffffffffu, w, i);
            float w1 = __shfl_sync(0xffffffffu, w, i + 1);
            float w2 = __shfl_sync(0xffffffffu, w, i + 2);
            float w3 = __shfl_sync(0xffffffffu, w, i + 3);
            if (act) {
                uint32_t u0 = g_t2h[(size_t)s0 * 20 + lane];
                uint32_t u1 = g_t2h[(size_t)s1 * 20 + lane];
                uint32_t u2 = g_t2h[(size_t)s2 * 20 + lane];
                uint32_t u3 = g_t2h[(size_t)s3 * 20 + lane];
                float2 v0 = __half22float2(*(const __half2*)&u0);
                float2 v1 = __half22float2(*(const __half2*)&u1);
                float2 v2 = __half22float2(*(const __half2*)&u2);
                float2 v3 = __half22float2(*(const __half2*)&u3);
                acc.x = fmaf(w0, v0.x, acc.x); acc.y = fmaf(w0, v0.y, acc.y);
                acc.x = fmaf(w1, v1.x, acc.x); acc.y = fmaf(w1, v1.y, acc.y);
                acc.x = fmaf(w2, v2.x, acc.x); acc.y = fmaf(w2, v2.y, acc.y);
                acc.x = fmaf(w3, v3.x, acc.x); acc.y = fmaf(w3, v3.y, acc.y);
            }
        }
        for (; i < cnt; ++i) {
            int   ss = __shfl_sync(0xffffffffu, s, i);
            float ww = __shfl_sync(0xffffffffu, w, i);
            if (act) {
                uint32_t u = g_t2h[(size_t)ss * 20 + lane];
                float2 v = __half22float2(*(const __half2*)&u);
                acc.x = fmaf(ww, v.x, acc.x);
                acc.y = fmaf(ww, v.y, acc.y);
            }
        }
    }

    if (act) {
        const int col = lane << 1;
        float2 b = *(const float2*)(b2 + col);
        float2 o = make_float2(acc.x + b.x, acc.y + b.y);
        *(float2*)(out + (size_t)gw * OUTF + col) = o;
    }
}

// ================= launch =================
extern "C" void kernel_launch(void* const* d_in, const int* in_sizes, int n_in,
                              void* d_out, int out_size)
{
    const float* x    = (const float*)d_in[0];
    const float* W1   = (const float*)d_in[1];
    const float* b1   = (const float*)d_in[2];
    const float* W2   = (const float*)d_in[3];
    const float* b2   = (const float*)d_in[4];
    const float* ew   = (const float*)d_in[5];
    const float* mask = (const float*)d_in[6];
    const int*   esrc = (const int*)d_in[7];
    const int*   edst = (const int*)d_in[8];
    float* out = (float*)d_out;

    const int M = in_sizes[0] / F_IN;   // 50000
    const int E = in_sizes[7];          // 800000

    const int nbM  = (M + NTILE - 1) / NTILE;
    const int nbE4 = (E / 4 + 255) / 256;

    // one-time setup (first call = correctness run, NOT captured)
    static cudaStream_t s_side = nullptr;
    static cudaEvent_t  s_fork = nullptr, s_join = nullptr;
    if (s_side == nullptr) {
        cudaFuncSetAttribute(gemm1_tc_kernel,
                             cudaFuncAttributeMaxDynamicSharedMemorySize, GEMM1_SMEM);
        cudaStreamCreateWithFlags(&s_side, cudaStreamNonBlocking);
        cudaEventCreateWithFlags(&s_fork, cudaEventDisableTiming);
        cudaEventCreateWithFlags(&s_join, cudaEventDisableTiming);
    }

    // fork: CSR chain (+cleanup) on side stream, concurrent with gemm1 on main
    cudaEventRecord(s_fork, 0);
    cudaStreamWaitEvent(s_side, s_fork, 0);
    hist_kernel<<<nbE4, 256, 0, s_side>>>(edst, E);
    scan_kernel<<<nbM, NTILE, 0, s_side>>>(M);
    fill_kernel<<<nbE4, 256, 0, s_side>>>(edst, esrc, ew, E);
    cleanup_kernel<<<nbM, 256, 0, s_side>>>(M);   // hidden under gemm1
    cudaEventRecord(s_join, s_side);

    // main: layer-1 dense path (independent of CSR)
    w1_prep_kernel<<<(F_IN * HID) / 256, 256>>>(W1);
    gemm1_tc_kernel<<<(M + 127) / 128, 256, GEMM1_SMEM>>>(x, M);

    // join: spmm1 needs both gemm1 (main) and CSR (side)
    cudaStreamWaitEvent(0, s_join, 0);
    spmm1_kernel<<<(M + 7) / 8, 256>>>(b1, mask, M);

    // layer 2
    gemm2_kernel<<<(M + 63) / 64, 256>>>(W2, M);
    spmm2_kernel<<<(M + 7) / 8, 256>>>(b2, out, M);
}